// round 6
// baseline (speedup 1.0000x reference)
#include <cuda_runtime.h>
#include <math_constants.h>
#include <stdint.h>

#define NROWS 16384
#define DIM   256
#define CSIZE 1024
#define NSTAGE 8
#define CAP   16
#define UBLK  2048
#define PITCH_A 260            // 256+4, %32==4 -> conflict-free frags
#define PITCH_B 36             // 32+4
#define NBUF  4
#define SMEM_DYN ((128 * PITCH_A + NBUF * 128 * PITCH_B) * 4)   // 206848 B

// Scratch (allocation-free)
__device__ float g_res[NROWS * DIM];
__device__ float g_rownorm[NROWS];
__device__ float g_cbnorm[NSTAGE * CSIZE];
__device__ int   g_cbmax[NSTAGE];
__device__ int   g_cand[NROWS * CAP];
__device__ int   g_candcnt[NROWS];
__device__ float g_losspart[NSTAGE * UBLK];

// ---------- helpers ----------
__device__ __forceinline__ uint32_t smem_u32(const void* p) {
    return (uint32_t)__cvta_generic_to_shared(p);
}
__device__ __forceinline__ void cp_async16(uint32_t saddr, const void* gptr) {
    asm volatile("cp.async.cg.shared.global [%0], [%1], 16;" :: "r"(saddr), "l"(gptr));
}
#define CP_COMMIT() asm volatile("cp.async.commit_group;")
#define CP_WAIT3()  asm volatile("cp.async.wait_group 3;")

__device__ __forceinline__ void mma_tf32(float& c0, float& c1, float& c2, float& c3,
                                         uint32_t a0, uint32_t a1, uint32_t a2, uint32_t a3,
                                         uint32_t b0, uint32_t b1) {
    asm("mma.sync.aligned.m16n8k8.row.col.f32.tf32.tf32.f32 "
        "{%0,%1,%2,%3}, {%4,%5,%6,%7}, {%8,%9}, {%0,%1,%2,%3};"
        : "+f"(c0), "+f"(c1), "+f"(c2), "+f"(c3)
        : "r"(a0), "r"(a1), "r"(a2), "r"(a3), "r"(b0), "r"(b1));
}
__device__ __forceinline__ int fkey(float f) {
    int i = __float_as_int(f);
    return i >= 0 ? i : i ^ 0x7FFFFFFF;
}
__device__ __forceinline__ float funkey(int i) {
    return __int_as_float(i >= 0 ? i : i ^ 0x7FFFFFFF);
}
__device__ __forceinline__ bool lt_vi(float v, int i, float w, int j) {
    return v < w || (v == w && i < j);
}

// ---------- init ----------
__global__ void init_kernel(const float* __restrict__ x, float* __restrict__ quant) {
    if (blockIdx.x == 0 && threadIdx.x < NSTAGE) g_cbmax[threadIdx.x] = 0;
    int i = blockIdx.x * blockDim.x + threadIdx.x;
    int stride = gridDim.x * blockDim.x;
    for (; i < NROWS * DIM; i += stride) {
        g_res[i] = x[i];
        quant[i] = 0.0f;
    }
}

// XLA-style row reduction of sum(v*v) — MUST stay bit-identical everywhere.
__device__ __forceinline__ float warp_rownorm(const float* __restrict__ p, int lane) {
    float acc = 0.0f;
#pragma unroll
    for (int i = 0; i < 8; i++) {
        float v = p[lane + 32 * i];
        acc = fmaf(v, v, acc);
    }
#pragma unroll
    for (int off = 16; off > 0; off >>= 1)
        acc += __shfl_down_sync(0xffffffffu, acc, off);
    return acc;
}

__global__ void cbnorm_kernel(const float* __restrict__ codebooks) {
    int row = blockIdx.x * 8 + (threadIdx.x >> 5);
    int lane = threadIdx.x & 31;
    if (row >= NSTAGE * CSIZE) return;
    float s = warp_rownorm(codebooks + (size_t)row * DIM, lane);
    if (lane == 0) {
        g_cbnorm[row] = s;
        atomicMax(&g_cbmax[row >> 10], __float_as_int(s));
    }
}

__global__ void rownorm_kernel() {
    int row = blockIdx.x * 8 + (threadIdx.x >> 5);
    int lane = threadIdx.x & 31;
    float s = warp_rownorm(g_res + (size_t)row * DIM, lane);
    if (lane == 0) g_rownorm[row] = s;
}

// ---------- screening: pipelined tf32 tensor GEMM + sound capture ----------
__global__ void __launch_bounds__(256, 1) screen_kernel(
    const float* __restrict__ codebooks, int stage)
{
    extern __shared__ uint32_t dyn[];
    uint32_t* As = dyn;                           // [128][PITCH_A] raw fp32 bits
    uint32_t* Bs = dyn + 128 * PITCH_A;           // [NBUF][128][PITCH_B]
    __shared__ int rowmin[128];
    __shared__ int rowcnt[128];
    __shared__ int rowlist[128 * CAP];

    const float* cb  = codebooks + (size_t)stage * CSIZE * DIM;
    const float* cbn = g_cbnorm + stage * CSIZE;

    const int tid  = threadIdx.x;
    const int lane = tid & 31;
    const int wid  = tid >> 5;
    const int wm   = wid >> 2;
    const int wn   = wid & 3;
    const int g    = lane >> 2;
    const int tg   = lane & 3;
    const int block_row = blockIdx.x * 128;

    const uint32_t sA = smem_u32(As);
    const uint32_t sB = smem_u32(Bs);

    if (tid < 128) { rowmin[tid] = 0x7F800000; rowcnt[tid] = 0; }

    // A tile resident: 128 rows x 256 k fp32 (group 0)
#pragma unroll
    for (int l = 0; l < 32; l++) {
        int idx = tid + l * 256;
        int r  = idx >> 6;
        int c4 = (idx & 63) << 2;
        cp_async16(sA + (uint32_t)(r * PITCH_A + c4) * 4,
                   &g_res[(size_t)(block_row + r) * DIM + c4]);
    }
    CP_COMMIT();

    // B chunk issue: chunk cc covers cb rows [(cc>>3)*128,+128), k [(cc&7)*32,+32)
    auto issue_chunk = [&](int cc) {
        int nrow = (cc >> 3) * 128;
        int kt   = (cc & 7) * 32;
        uint32_t bbase = sB + (uint32_t)((cc & 3) * 128 * PITCH_B) * 4;
#pragma unroll
        for (int l = 0; l < 4; l++) {
            int idx = tid + l * 256;
            int r  = idx >> 3;
            int c4 = (idx & 7) << 2;
            cp_async16(bbase + (uint32_t)(r * PITCH_B + c4) * 4,
                       &cb[(size_t)(nrow + r) * DIM + kt + c4]);
        }
    };
#pragma unroll
    for (int p = 0; p < 3; p++) { issue_chunk(p); CP_COMMIT(); }

    const float cbmaxf = __int_as_float(g_cbmax[stage]);
    int   rloc[8];
    float rn8[8], m2[8];
#pragma unroll
    for (int mi = 0; mi < 4; mi++)
#pragma unroll
        for (int h = 0; h < 2; h++) {
            int j = mi * 2 + h;
            int rl = wm * 64 + mi * 16 + g + h * 8;
            rloc[j] = rl;
            float rv = g_rownorm[block_row + rl];
            rn8[j] = rv;
            // truncation-mode margin: 2 * 2^-7 * sqrt(rn*cnmax) = 4x error bound
            m2[j] = 2.0f * 0.0078125f * sqrtf(rv * cbmaxf);
        }

    float acc[4][4][4];
#pragma unroll
    for (int mi = 0; mi < 4; mi++)
#pragma unroll
        for (int ni = 0; ni < 4; ni++)
#pragma unroll
            for (int e = 0; e < 4; e++) acc[mi][ni][e] = 0.0f;

    for (int c = 0; c < 64; c++) {
        if (c + 3 < 64) issue_chunk(c + 3);
        CP_COMMIT();               // one group per iteration (maybe empty)
        CP_WAIT3();                // in-order retirement: A + B0..Bc complete
        __syncthreads();

        const int kb_base = (c & 7) * 32;
        const uint32_t* Bbuf = Bs + (c & 3) * 128 * PITCH_B;
#pragma unroll
        for (int ks = 0; ks < 4; ks++) {
            const int kbA = kb_base + ks * 8;
            const int kbB = ks * 8;
            uint32_t a[4][4], b[4][2];
#pragma unroll
            for (int mi = 0; mi < 4; mi++) {
                int m = wm * 64 + mi * 16 + g;
                a[mi][0] = As[m * PITCH_A + kbA + tg];
                a[mi][1] = As[(m + 8) * PITCH_A + kbA + tg];
                a[mi][2] = As[m * PITCH_A + kbA + tg + 4];
                a[mi][3] = As[(m + 8) * PITCH_A + kbA + tg + 4];
            }
#pragma unroll
            for (int ni = 0; ni < 4; ni++) {
                int n = wn * 32 + ni * 8 + g;
                b[ni][0] = Bbuf[n * PITCH_B + kbB + tg];
                b[ni][1] = Bbuf[n * PITCH_B + kbB + tg + 4];
            }
#pragma unroll
            for (int mi = 0; mi < 4; mi++)
#pragma unroll
                for (int ni = 0; ni < 4; ni++)
                    mma_tf32(acc[mi][ni][0], acc[mi][ni][1], acc[mi][ni][2], acc[mi][ni][3],
                             a[mi][0], a[mi][1], a[mi][2], a[mi][3],
                             b[ni][0], b[ni][1]);
        }
        __syncthreads();           // all reads of buf (c&3) done before reuse

        if ((c & 7) == 7) {
            // ---- epilogue for this 128-column block ----
            const int nccol = (c >> 3) * 128;
            float cnv[4][2];
#pragma unroll
            for (int ni = 0; ni < 4; ni++) {
                int cc = nccol + wn * 32 + ni * 8 + tg * 2;
                cnv[ni][0] = cbn[cc];
                cnv[ni][1] = cbn[cc + 1];
            }
            float locmin[8];
#pragma unroll
            for (int j = 0; j < 8; j++) locmin[j] = CUDART_INF_F;
#pragma unroll
            for (int mi = 0; mi < 4; mi++)
#pragma unroll
                for (int ni = 0; ni < 4; ni++)
#pragma unroll
                    for (int h = 0; h < 2; h++)
#pragma unroll
                        for (int w = 0; w < 2; w++) {
                            float s = (rn8[mi * 2 + h] - 2.0f * acc[mi][ni][h * 2 + w]) + cnv[ni][w];
                            if (s < locmin[mi * 2 + h]) locmin[mi * 2 + h] = s;
                        }
#pragma unroll
            for (int j = 0; j < 8; j++) atomicMin(&rowmin[rloc[j]], fkey(locmin[j]));
            __syncthreads();

            float thr[8];
#pragma unroll
            for (int j = 0; j < 8; j++) thr[j] = funkey(rowmin[rloc[j]]) + m2[j];
#pragma unroll
            for (int mi = 0; mi < 4; mi++)
#pragma unroll
                for (int ni = 0; ni < 4; ni++)
#pragma unroll
                    for (int h = 0; h < 2; h++)
#pragma unroll
                        for (int w = 0; w < 2; w++) {
                            int j = mi * 2 + h;
                            float s = (rn8[j] - 2.0f * acc[mi][ni][h * 2 + w]) + cnv[ni][w];
                            if (s < thr[j]) {
                                int col = nccol + wn * 32 + ni * 8 + tg * 2 + w;
                                int p = atomicAdd(&rowcnt[rloc[j]], 1);
                                if (p < CAP) rowlist[rloc[j] * CAP + p] = col;
                            }
                        }
            __syncthreads();

            // reset accumulators for next column block
#pragma unroll
            for (int mi = 0; mi < 4; mi++)
#pragma unroll
                for (int ni = 0; ni < 4; ni++)
#pragma unroll
                    for (int e = 0; e < 4; e++) acc[mi][ni][e] = 0.0f;
        }
    }

    if (tid < 128) g_candcnt[block_row + tid] = rowcnt[tid];
    for (int i = tid; i < 128 * CAP; i += 256)
        g_cand[(size_t)block_row * CAP + i] = rowlist[i];
}

// ---------- finish: exact rescreen + update + loss + next rownorm ----------
__global__ void finish_kernel(const float* __restrict__ codebooks,
                              float* __restrict__ out, int stage)
{
    const float* cb  = codebooks + (size_t)stage * CSIZE * DIM;
    const float* cbn = g_cbnorm + stage * CSIZE;
    float* enc_out = out + 2;
    float* quant   = out + 2 + NROWS * NSTAGE;
    __shared__ float ws[8];

    int row  = blockIdx.x * 8 + (threadIdx.x >> 5);
    int lane = threadIdx.x & 31;
    const float* rrow = &g_res[(size_t)row * DIM];
    float rn = g_rownorm[row];
    int cnt = g_candcnt[row];

    float bestv = CUDART_INF_F;
    int   besti = 0x7FFFFFFF;

    if (cnt <= CAP) {
        if (lane < cnt) {
            int c = g_cand[row * CAP + lane];
            const float* crow = &cb[(size_t)c * DIM];
            float t = 0.0f;
#pragma unroll 8
            for (int k = 0; k < DIM; k++) t = fmaf(rrow[k], crow[k], t);
            bestv = __fadd_rn(__fsub_rn(rn, 2.0f * t), cbn[c]);
            besti = c;
        }
    } else {
        for (int c = lane; c < CSIZE; c += 32) {
            const float* crow = &cb[(size_t)c * DIM];
            float t = 0.0f;
#pragma unroll 8
            for (int k = 0; k < DIM; k++) t = fmaf(rrow[k], crow[k], t);
            float s = __fadd_rn(__fsub_rn(rn, 2.0f * t), cbn[c]);
            if (lt_vi(s, c, bestv, besti)) { bestv = s; besti = c; }
        }
    }
#pragma unroll
    for (int o = 16; o > 0; o >>= 1) {
        float ov = __shfl_down_sync(0xffffffffu, bestv, o);
        int   oi = __shfl_down_sync(0xffffffffu, besti, o);
        if (lt_vi(ov, oi, bestv, besti)) { bestv = ov; besti = oi; }
    }
    besti = __shfl_sync(0xffffffffu, besti, 0);
    if (lane == 0)
        enc_out[(size_t)row * NSTAGE + stage] = (float)besti;

    // fused update (bit-exact strided order for rownorm chain)
    size_t rb  = (size_t)row * DIM;
    size_t cbb = (size_t)besti * DIM;
    float acc = 0.0f;
#pragma unroll
    for (int i = 0; i < 8; i++) {
        int d = lane + 32 * i;
        float nv = cb[cbb + d];
        float diff = g_res[rb + d] - nv;
        g_res[rb + d] = diff;
        quant[rb + d] += nv;
        acc = fmaf(diff, diff, acc);
    }
#pragma unroll
    for (int o = 16; o > 0; o >>= 1)
        acc += __shfl_down_sync(0xffffffffu, acc, o);
    if (lane == 0) {
        g_rownorm[row] = acc;
        ws[threadIdx.x >> 5] = acc;
    }
    __syncthreads();
    if (threadIdx.x == 0) {
        float t = 0.0f;
#pragma unroll
        for (int w = 0; w < 8; w++) t += ws[w];
        g_losspart[stage * UBLK + blockIdx.x] = t;
    }
}

// ---------- loss finalize ----------
__global__ void finalize_kernel(float* __restrict__ out) {
    __shared__ float s[256];
    float t = 0.0f;
    for (int i = threadIdx.x; i < NSTAGE * UBLK; i += 256)
        t += g_losspart[i];
    s[threadIdx.x] = t;
    __syncthreads();
    for (int o = 128; o > 0; o >>= 1) {
        if (threadIdx.x < o) s[threadIdx.x] += s[threadIdx.x + o];
        __syncthreads();
    }
    if (threadIdx.x == 0) {
        float loss = s[0] / (float)((size_t)NROWS * DIM);
        out[0] = loss;
        out[1] = loss;
    }
}

extern "C" void kernel_launch(void* const* d_in, const int* in_sizes, int n_in,
                              void* d_out, int out_size) {
    const float* x         = (const float*)d_in[0];
    const float* codebooks = (const float*)d_in[1];
    float* out = (float*)d_out;

    cudaFuncSetAttribute(screen_kernel,
                         cudaFuncAttributeMaxDynamicSharedMemorySize, SMEM_DYN);

    init_kernel<<<512, 256>>>(x, out + 2 + NROWS * NSTAGE);
    cbnorm_kernel<<<(NSTAGE * CSIZE) / 8, 256>>>(codebooks);
    rownorm_kernel<<<NROWS / 8, 256>>>();
    for (int s = 0; s < NSTAGE; s++) {
        screen_kernel<<<NROWS / 128, 256, SMEM_DYN>>>(codebooks, s);
        finish_kernel<<<UBLK, 256>>>(codebooks, out, s);
    }
    finalize_kernel<<<1, 256>>>(out);
}

// round 7
// speedup vs baseline: 1.6949x; 1.6949x over previous
#include <cuda_runtime.h>
#include <math_constants.h>
#include <stdint.h>

#define NROWS 16384
#define DIM   256
#define CSIZE 1024
#define NSTAGE 8
#define CAP   24
#define PITCH_A 260            // 256+4, %32==4 -> conflict-free frags
#define PITCH_B 36             // 32+4
#define NBUF  4
#define NBLK  (NROWS / 128)    // 128
#define SMEM_DYN ((128 * PITCH_A + NBUF * 128 * PITCH_B) * 4)   // 206848 B

// Scratch (allocation-free)
__device__ float g_res[NROWS * DIM];
__device__ float g_rownorm[NROWS];
__device__ float g_cbnorm[NSTAGE * CSIZE];
__device__ int   g_cbmax[NSTAGE];
__device__ float g_losspart[NSTAGE * NBLK];

// ---------- helpers ----------
__device__ __forceinline__ uint32_t smem_u32(const void* p) {
    return (uint32_t)__cvta_generic_to_shared(p);
}
__device__ __forceinline__ void cp_async16(uint32_t saddr, const void* gptr) {
    asm volatile("cp.async.cg.shared.global [%0], [%1], 16;" :: "r"(saddr), "l"(gptr));
}
#define CP_COMMIT() asm volatile("cp.async.commit_group;")
#define CP_WAIT3()  asm volatile("cp.async.wait_group 3;")

__device__ __forceinline__ uint32_t f2tf32(float f) {
    uint32_t r;
    asm("cvt.rna.tf32.f32 %0, %1;" : "=r"(r) : "f"(f));
    return r;
}
__device__ __forceinline__ uint32_t bits2tf32(uint32_t raw) {
    return f2tf32(__int_as_float(raw));
}
__device__ __forceinline__ void mma_tf32(float& c0, float& c1, float& c2, float& c3,
                                         uint32_t a0, uint32_t a1, uint32_t a2, uint32_t a3,
                                         uint32_t b0, uint32_t b1) {
    asm("mma.sync.aligned.m16n8k8.row.col.f32.tf32.tf32.f32 "
        "{%0,%1,%2,%3}, {%4,%5,%6,%7}, {%8,%9}, {%0,%1,%2,%3};"
        : "+f"(c0), "+f"(c1), "+f"(c2), "+f"(c3)
        : "r"(a0), "r"(a1), "r"(a2), "r"(a3), "r"(b0), "r"(b1));
}
__device__ __forceinline__ int fkey(float f) {
    int i = __float_as_int(f);
    return i >= 0 ? i : i ^ 0x7FFFFFFF;
}
__device__ __forceinline__ float funkey(int i) {
    return __int_as_float(i >= 0 ? i : i ^ 0x7FFFFFFF);
}
__device__ __forceinline__ bool lt_vi(float v, int i, float w, int j) {
    return v < w || (v == w && i < j);
}

// ---------- init ----------
__global__ void init_kernel(const float* __restrict__ x, float* __restrict__ quant) {
    if (blockIdx.x == 0 && threadIdx.x < NSTAGE) g_cbmax[threadIdx.x] = 0;
    int i = blockIdx.x * blockDim.x + threadIdx.x;
    int stride = gridDim.x * blockDim.x;
    for (; i < NROWS * DIM; i += stride) {
        g_res[i] = x[i];
        quant[i] = 0.0f;
    }
}

// XLA-style row reduction of sum(v*v) — MUST stay bit-identical everywhere.
__device__ __forceinline__ float warp_rownorm(const float* __restrict__ p, int lane) {
    float acc = 0.0f;
#pragma unroll
    for (int i = 0; i < 8; i++) {
        float v = p[lane + 32 * i];
        acc = fmaf(v, v, acc);
    }
#pragma unroll
    for (int off = 16; off > 0; off >>= 1)
        acc += __shfl_down_sync(0xffffffffu, acc, off);
    return acc;
}

__global__ void cbnorm_kernel(const float* __restrict__ codebooks) {
    int row = blockIdx.x * 8 + (threadIdx.x >> 5);
    int lane = threadIdx.x & 31;
    if (row >= NSTAGE * CSIZE) return;
    float s = warp_rownorm(codebooks + (size_t)row * DIM, lane);
    if (lane == 0) {
        g_cbnorm[row] = s;
        atomicMax(&g_cbmax[row >> 10], __float_as_int(s));
    }
}

__global__ void rownorm_kernel() {
    int row = blockIdx.x * 8 + (threadIdx.x >> 5);
    int lane = threadIdx.x & 31;
    float s = warp_rownorm(g_res + (size_t)row * DIM, lane);
    if (lane == 0) g_rownorm[row] = s;
}

// ---------- fused stage: tf32 screen + exact rescreen + update ----------
__global__ void __launch_bounds__(256, 1) stage_kernel(
    const float* __restrict__ codebooks, float* __restrict__ out, int stage)
{
    extern __shared__ uint32_t dyn[];
    uint32_t* As = dyn;                           // [128][PITCH_A] raw fp32 bits (exact res)
    uint32_t* Bs = dyn + 128 * PITCH_A;           // [NBUF][128][PITCH_B] raw fp32 bits
    __shared__ int rowmin[128];
    __shared__ int rowcnt[128];
    __shared__ int rowlist[128 * CAP];
    __shared__ float ws[8];

    const float* cb  = codebooks + (size_t)stage * CSIZE * DIM;
    const float* cbn = g_cbnorm + stage * CSIZE;
    float* enc_out = out + 2;
    float* quant   = out + 2 + NROWS * NSTAGE;

    const int tid  = threadIdx.x;
    const int lane = tid & 31;
    const int wid  = tid >> 5;
    const int wm   = wid >> 2;
    const int wn   = wid & 3;
    const int g    = lane >> 2;
    const int tg   = lane & 3;
    const int block_row = blockIdx.x * 128;

    const uint32_t sA = smem_u32(As);
    const uint32_t sB = smem_u32(Bs);

    if (tid < 128) { rowmin[tid] = 0x7F800000; rowcnt[tid] = 0; }

    // A tile resident: 128 rows x 256 k raw fp32 (group 0)
#pragma unroll
    for (int l = 0; l < 32; l++) {
        int idx = tid + l * 256;
        int r  = idx >> 6;
        int c4 = (idx & 63) << 2;
        cp_async16(sA + (uint32_t)(r * PITCH_A + c4) * 4,
                   &g_res[(size_t)(block_row + r) * DIM + c4]);
    }
    CP_COMMIT();

    // B chunk cc: cb rows [(cc>>3)*128,+128), k [(cc&7)*32,+32)
    auto issue_chunk = [&](int cc) {
        int nrow = (cc >> 3) * 128;
        int kt   = (cc & 7) * 32;
        uint32_t bbase = sB + (uint32_t)((cc & 3) * 128 * PITCH_B) * 4;
#pragma unroll
        for (int l = 0; l < 4; l++) {
            int idx = tid + l * 256;
            int r  = idx >> 3;
            int c4 = (idx & 7) << 2;
            cp_async16(bbase + (uint32_t)(r * PITCH_B + c4) * 4,
                       &cb[(size_t)(nrow + r) * DIM + kt + c4]);
        }
    };
#pragma unroll
    for (int p = 0; p < 3; p++) { issue_chunk(p); CP_COMMIT(); }

    const float cbmaxf = __int_as_float(g_cbmax[stage]);
    int   rloc[8];
    float rn8[8], m2[8];
#pragma unroll
    for (int mi = 0; mi < 4; mi++)
#pragma unroll
        for (int h = 0; h < 2; h++) {
            int j = mi * 2 + h;
            int rl = wm * 64 + mi * 16 + g + h * 8;
            rloc[j] = rl;
            float rv = g_rownorm[block_row + rl];
            rn8[j] = rv;
            // rna-mode margin: 2 * 2^-8 * sqrt(rn*cnmax)  (~5x error bound, proven R5)
            m2[j] = 2.0f * 0.00390625f * sqrtf(rv * cbmaxf);
        }

    float acc[4][4][4];
#pragma unroll
    for (int mi = 0; mi < 4; mi++)
#pragma unroll
        for (int ni = 0; ni < 4; ni++)
#pragma unroll
            for (int e = 0; e < 4; e++) acc[mi][ni][e] = 0.0f;

    for (int c = 0; c < 64; c++) {
        if (c + 3 < 64) issue_chunk(c + 3);
        CP_COMMIT();               // one group per iteration (maybe empty)
        CP_WAIT3();                // in-order retirement: A + B0..Bc complete
        __syncthreads();

        const int kb_base = (c & 7) * 32;
        const uint32_t* Bbuf = Bs + (c & 3) * 128 * PITCH_B;
#pragma unroll
        for (int ks = 0; ks < 4; ks++) {
            const int kbA = kb_base + ks * 8;
            const int kbB = ks * 8;
            uint32_t a[4][4], b[4][2];
#pragma unroll
            for (int mi = 0; mi < 4; mi++) {
                int m = wm * 64 + mi * 16 + g;
                a[mi][0] = bits2tf32(As[m * PITCH_A + kbA + tg]);
                a[mi][1] = bits2tf32(As[(m + 8) * PITCH_A + kbA + tg]);
                a[mi][2] = bits2tf32(As[m * PITCH_A + kbA + tg + 4]);
                a[mi][3] = bits2tf32(As[(m + 8) * PITCH_A + kbA + tg + 4]);
            }
#pragma unroll
            for (int ni = 0; ni < 4; ni++) {
                int n = wn * 32 + ni * 8 + g;
                b[ni][0] = bits2tf32(Bbuf[n * PITCH_B + kbB + tg]);
                b[ni][1] = bits2tf32(Bbuf[n * PITCH_B + kbB + tg + 4]);
            }
#pragma unroll
            for (int mi = 0; mi < 4; mi++)
#pragma unroll
                for (int ni = 0; ni < 4; ni++)
                    mma_tf32(acc[mi][ni][0], acc[mi][ni][1], acc[mi][ni][2], acc[mi][ni][3],
                             a[mi][0], a[mi][1], a[mi][2], a[mi][3],
                             b[ni][0], b[ni][1]);
        }
        __syncthreads();           // reads of buf (c&3) done before reuse

        if ((c & 7) == 7) {
            // ---- epilogue for this 128-column block ----
            const int nccol = (c >> 3) * 128;
            float cnv[4][2];
#pragma unroll
            for (int ni = 0; ni < 4; ni++) {
                int cc = nccol + wn * 32 + ni * 8 + tg * 2;
                cnv[ni][0] = cbn[cc];
                cnv[ni][1] = cbn[cc + 1];
            }
            float locmin[8];
#pragma unroll
            for (int j = 0; j < 8; j++) locmin[j] = CUDART_INF_F;
#pragma unroll
            for (int mi = 0; mi < 4; mi++)
#pragma unroll
                for (int ni = 0; ni < 4; ni++)
#pragma unroll
                    for (int h = 0; h < 2; h++)
#pragma unroll
                        for (int w = 0; w < 2; w++) {
                            float s = (rn8[mi * 2 + h] - 2.0f * acc[mi][ni][h * 2 + w]) + cnv[ni][w];
                            if (s < locmin[mi * 2 + h]) locmin[mi * 2 + h] = s;
                        }
#pragma unroll
            for (int j = 0; j < 8; j++) atomicMin(&rowmin[rloc[j]], fkey(locmin[j]));
            __syncthreads();

            float thr[8];
#pragma unroll
            for (int j = 0; j < 8; j++) thr[j] = funkey(rowmin[rloc[j]]) + m2[j];
#pragma unroll
            for (int mi = 0; mi < 4; mi++)
#pragma unroll
                for (int ni = 0; ni < 4; ni++)
#pragma unroll
                    for (int h = 0; h < 2; h++)
#pragma unroll
                        for (int w = 0; w < 2; w++) {
                            int j = mi * 2 + h;
                            float s = (rn8[j] - 2.0f * acc[mi][ni][h * 2 + w]) + cnv[ni][w];
                            if (s < thr[j]) {
                                int col = nccol + wn * 32 + ni * 8 + tg * 2 + w;
                                int p = atomicAdd(&rowcnt[rloc[j]], 1);
                                if (p < CAP) rowlist[rloc[j] * CAP + p] = col;
                            }
                        }
            __syncthreads();

#pragma unroll
            for (int mi = 0; mi < 4; mi++)
#pragma unroll
                for (int ni = 0; ni < 4; ni++)
#pragma unroll
                    for (int e = 0; e < 4; e++) acc[mi][ni][e] = 0.0f;
        }
    }

    // ======== fused finish: exact rescreen + update, warp per row ========
    float warp_loss = 0.0f;
    for (int rr = 0; rr < 16; rr++) {
        int row  = wid * 16 + rr;
        int grow = block_row + row;
        const float* arow = (const float*)&As[row * PITCH_A];  // exact res bits
        float rn = g_rownorm[grow];
        int cnt = rowcnt[row];

        float bestv = CUDART_INF_F;
        int   besti = 0x7FFFFFFF;
        if (cnt <= CAP) {
            if (lane < cnt) {
                int cidx = rowlist[row * CAP + lane];
                const float* crow = &cb[(size_t)cidx * DIM];
                float t = 0.0f;
#pragma unroll 8
                for (int k = 0; k < DIM; k++) t = fmaf(arow[k], crow[k], t);
                bestv = __fadd_rn(__fsub_rn(rn, 2.0f * t), cbn[cidx]);
                besti = cidx;
            }
        } else {
            for (int cidx = lane; cidx < CSIZE; cidx += 32) {
                const float* crow = &cb[(size_t)cidx * DIM];
                float t = 0.0f;
#pragma unroll 8
                for (int k = 0; k < DIM; k++) t = fmaf(arow[k], crow[k], t);
                float s = __fadd_rn(__fsub_rn(rn, 2.0f * t), cbn[cidx]);
                if (lt_vi(s, cidx, bestv, besti)) { bestv = s; besti = cidx; }
            }
        }
#pragma unroll
        for (int o = 16; o > 0; o >>= 1) {
            float ov = __shfl_down_sync(0xffffffffu, bestv, o);
            int   oi = __shfl_down_sync(0xffffffffu, besti, o);
            if (lt_vi(ov, oi, bestv, besti)) { bestv = ov; besti = oi; }
        }
        besti = __shfl_sync(0xffffffffu, besti, 0);
        if (lane == 0)
            enc_out[(size_t)grow * NSTAGE + stage] = (float)besti;

        // bit-exact update (strided order matches warp_rownorm)
        size_t rb  = (size_t)grow * DIM;
        size_t cbb = (size_t)besti * DIM;
        float lacc = 0.0f;
#pragma unroll
        for (int i = 0; i < 8; i++) {
            int d = lane + 32 * i;
            float nv = cb[cbb + d];
            float diff = arow[d] - nv;
            g_res[rb + d] = diff;
            quant[rb + d] += nv;
            lacc = fmaf(diff, diff, lacc);
        }
#pragma unroll
        for (int o = 16; o > 0; o >>= 1)
            lacc += __shfl_down_sync(0xffffffffu, lacc, o);
        if (lane == 0) {
            g_rownorm[grow] = lacc;
            warp_loss += lacc;
        }
    }
    if (lane == 0) ws[wid] = warp_loss;
    __syncthreads();
    if (tid == 0) {
        float t = 0.0f;
#pragma unroll
        for (int w = 0; w < 8; w++) t += ws[w];
        g_losspart[stage * NBLK + blockIdx.x] = t;
    }
}

// ---------- loss finalize ----------
__global__ void finalize_kernel(float* __restrict__ out) {
    __shared__ float s[256];
    float t = 0.0f;
    for (int i = threadIdx.x; i < NSTAGE * NBLK; i += 256)
        t += g_losspart[i];
    s[threadIdx.x] = t;
    __syncthreads();
    for (int o = 128; o > 0; o >>= 1) {
        if (threadIdx.x < o) s[threadIdx.x] += s[threadIdx.x + o];
        __syncthreads();
    }
    if (threadIdx.x == 0) {
        float loss = s[0] / (float)((size_t)NROWS * DIM);
        out[0] = loss;
        out[1] = loss;
    }
}

extern "C" void kernel_launch(void* const* d_in, const int* in_sizes, int n_in,
                              void* d_out, int out_size) {
    const float* x         = (const float*)d_in[0];
    const float* codebooks = (const float*)d_in[1];
    float* out = (float*)d_out;

    cudaFuncSetAttribute(stage_kernel,
                         cudaFuncAttributeMaxDynamicSharedMemorySize, SMEM_DYN);

    init_kernel<<<512, 256>>>(x, out + 2 + NROWS * NSTAGE);
    cbnorm_kernel<<<(NSTAGE * CSIZE) / 8, 256>>>(codebooks);
    rownorm_kernel<<<NROWS / 8, 256>>>();
    for (int s = 0; s < NSTAGE; s++)
        stage_kernel<<<NBLK, 256, SMEM_DYN>>>(codebooks, out, s);
    finalize_kernel<<<1, 256>>>(out);
}